// round 10
// baseline (speedup 1.0000x reference)
#include <cuda_runtime.h>
#include <cstdint>

#define NQ     128
#define NK     2048
#define D5     768
#define SEQ    32
#define ZD     24
#define NTHR   256
#define KCHUNK 32
#define NB     8
#define NBATCH (KCHUNK / NB)

// per-buffer u64s: NB rows * 2 ksteps * 32 s * 4 j
#define BUF_U64 (NB * 2 * 32 * 4)          // 2048
#define SMEM_BYTES (2 * BUF_U64 * 8)       // 32768

typedef unsigned long long ull;

__device__ __forceinline__ uint32_t pk(float lo, float hi) {
    uint32_t r; asm("cvt.rn.bf16x2.f32 %0, %1, %2;" : "=r"(r) : "f"(hi), "f"(lo));
    return r;
}

// 3-input float max (sm_90+ baseline PTX -> FMNMX3)
__device__ __forceinline__ float fmax3(float a, float b, float c) {
    float d; asm("max.f32 %0, %1, %2, %3;" : "=f"(d) : "f"(a), "f"(b), "f"(c));
    return d;
}

__device__ __forceinline__ void mma16_z(float* c, const uint32_t* a, ull b) {
    uint32_t b0 = (uint32_t)b, b1 = (uint32_t)(b >> 32);
    asm volatile(
        "mma.sync.aligned.m16n8k16.row.col.f32.bf16.bf16.f32 "
        "{%0,%1,%2,%3}, {%4,%5,%6,%7}, {%8,%9}, {%10,%10,%10,%10};"
        : "=f"(c[0]), "=f"(c[1]), "=f"(c[2]), "=f"(c[3])
        : "r"(a[0]), "r"(a[1]), "r"(a[2]), "r"(a[3]), "r"(b0), "r"(b1), "f"(0.0f));
}
__device__ __forceinline__ void mma16(float* c, const uint32_t* a, ull b) {
    uint32_t b0 = (uint32_t)b, b1 = (uint32_t)(b >> 32);
    asm volatile(
        "mma.sync.aligned.m16n8k16.row.col.f32.bf16.bf16.f32 "
        "{%0,%1,%2,%3}, {%4,%5,%6,%7}, {%8,%9}, {%0,%1,%2,%3};"
        : "+f"(c[0]), "+f"(c[1]), "+f"(c[2]), "+f"(c[3])
        : "r"(a[0]), "r"(a[1]), "r"(a[2]), "r"(a[3]), "r"(b0), "r"(b1));
}

// Stage NB memory rows as bf16, zipped so each B fragment is one LDS.64.
__device__ __forceinline__ void stage(ull* __restrict__ buf,
                                      const float* __restrict__ kbase, int tid) {
    int kk = tid >> 5, s = tid & 31;
    const float4* p = reinterpret_cast<const float4*>(kbase + kk * D5 + s * ZD);
    float4 x0 = p[0], x1 = p[1], x2 = p[2], x3 = p[3], x4 = p[4], x5 = p[5];
    uint32_t p0 = pk(x0.x, x0.y), p1 = pk(x0.z, x0.w);
    uint32_t p2 = pk(x1.x, x1.y), p3 = pk(x1.z, x1.w);
    uint32_t p4 = pk(x2.x, x2.y), p5 = pk(x2.z, x2.w);
    uint32_t p6 = pk(x3.x, x3.y), p7 = pk(x3.z, x3.w);
    uint32_t p8 = pk(x4.x, x4.y), p9 = pk(x4.z, x4.w);
    uint32_t pA = pk(x5.x, x5.y), pB = pk(x5.z, x5.w);
    ulonglong2* d0 = reinterpret_cast<ulonglong2*>(buf + ((size_t)(kk * 2) * 32 + s) * 4);
    d0[0] = make_ulonglong2((ull)p0 | ((ull)p4 << 32), (ull)p1 | ((ull)p5 << 32));
    d0[1] = make_ulonglong2((ull)p2 | ((ull)p6 << 32), (ull)p3 | ((ull)p7 << 32));
    ulonglong2* d1 = reinterpret_cast<ulonglong2*>(buf + ((size_t)(kk * 2 + 1) * 32 + s) * 4);
    d1[0] = make_ulonglong2((ull)p8, (ull)p9);
    d1[1] = make_ulonglong2((ull)pA, (ull)pB);
}

extern __shared__ ull sbuf[];

__global__ __launch_bounds__(NTHR, 3)
void matcher_hmma(const float* __restrict__ tgt,
                  const float* __restrict__ mem,
                  float* __restrict__ out)
{
    const int tid  = threadIdx.x;
    const int warp = tid >> 5;
    const int lane = tid & 31;
    const int gr   = lane >> 2;
    const int gc   = lane & 3;

    const int q0 = (blockIdx.x >> 6) * 8;       // 16 q-chunks
    const int k0 = (blockIdx.x & 63) * KCHUNK;  // 64 k-chunks
    const int q  = q0 + warp;

    // A fragments (bf16 pairs), resident: [mi][ks][4]
    uint32_t afr[2][2][4];
    {
        const float* a = tgt + (size_t)q * D5;
        #pragma unroll
        for (int mi = 0; mi < 2; ++mi) {
            int r = gr + 16 * mi;
            const float* r0 = a + r * ZD;
            const float* r1 = a + (r + 8) * ZD;
            afr[mi][0][0] = pk(r0[2 * gc],      r0[2 * gc + 1]);
            afr[mi][0][1] = pk(r1[2 * gc],      r1[2 * gc + 1]);
            afr[mi][0][2] = pk(r0[2 * gc + 8],  r0[2 * gc + 9]);
            afr[mi][0][3] = pk(r1[2 * gc + 8],  r1[2 * gc + 9]);
            afr[mi][1][0] = pk(r0[2 * gc + 16], r0[2 * gc + 17]);
            afr[mi][1][1] = pk(r1[2 * gc + 16], r1[2 * gc + 17]);
            afr[mi][1][2] = 0u;
            afr[mi][1][3] = 0u;
        }
    }

    float* __restrict__ out0 = out + (size_t)q * NK;
    float* __restrict__ out1 = out0 + (size_t)NQ * NK;

    stage(sbuf, mem + (size_t)k0 * D5, tid);
    __syncthreads();

    const int p0b = (lane >> 2) & 1;
    const int p1b = (lane >> 3) & 1;
    const int p2b = (lane >> 4) & 1;
    const int q0b = lane & 1;
    const int q1b = (lane >> 1) & 1;

    for (int b = 0; b < NBATCH; ++b) {
        ull* __restrict__ cur = sbuf + (size_t)(b & 1) * BUF_U64;
        if (b + 1 < NBATCH)
            stage(sbuf + (size_t)((b + 1) & 1) * BUF_U64,
                  mem + (size_t)(k0 + (b + 1) * NB) * D5, tid);

        float part[NB];

        #pragma unroll 1
        for (int kk = 0; kk < NB; ++kk) {
            const ull* __restrict__ bb = cur + (size_t)kk * 256;
            ull bf0[4], bf1[4];
            #pragma unroll
            for (int ni = 0; ni < 4; ++ni) {
                bf0[ni] = bb[(gr + 8 * ni) * 4 + gc];
                bf1[ni] = bb[(32 + gr + 8 * ni) * 4 + gc];
            }
            float acc[2][4][4];
            #pragma unroll
            for (int mi = 0; mi < 2; ++mi)
                #pragma unroll
                for (int ni = 0; ni < 4; ++ni) {
                    mma16_z(acc[mi][ni], afr[mi][0], bf0[ni]);
                    mma16(acc[mi][ni], afr[mi][1], bf1[ni]);
                }

            // ---- In-thread row maxes (4 slots over 8 cols, FMNMX3 trees) ----
            float rm[4];
            #pragma unroll
            for (int mi = 0; mi < 2; ++mi)
                #pragma unroll
                for (int h = 0; h < 2; ++h) {
                    float m = fmax3(acc[mi][0][2 * h], acc[mi][0][2 * h + 1],
                                    acc[mi][1][2 * h]);
                    m = fmax3(m, acc[mi][1][2 * h + 1], acc[mi][2][2 * h]);
                    m = fmax3(m, acc[mi][2][2 * h + 1], acc[mi][3][2 * h]);
                    rm[2 * mi + h] = fmaxf(m, acc[mi][3][2 * h + 1]);
                }
            // ---- In-thread col maxes (8 slots over 4 rows, FMNMX3) ----
            float cm[8];
            #pragma unroll
            for (int ni = 0; ni < 4; ++ni)
                #pragma unroll
                for (int p = 0; p < 2; ++p) {
                    float m = fmax3(acc[0][ni][p], acc[0][ni][p + 2], acc[1][ni][p]);
                    cm[ni * 2 + p] = fmaxf(m, acc[1][ni][p + 2]);
                }

            // ---- Reduce-scatter: rows over gc bits (xor 1,2) ----
            float row_own;
            {
                float s0 = q0b ? rm[0] : rm[2], k0v = q0b ? rm[2] : rm[0];
                float s1 = q0b ? rm[1] : rm[3], k1v = q0b ? rm[3] : rm[1];
                float w0 = fmaxf(k0v, __shfl_xor_sync(0xffffffffu, s0, 1));
                float w1 = fmaxf(k1v, __shfl_xor_sync(0xffffffffu, s1, 1));
                float s2 = q1b ? w0 : w1, k2v = q1b ? w1 : w0;
                row_own = fmaxf(k2v, __shfl_xor_sync(0xffffffffu, s2, 2));
            }
            // ---- Reduce-scatter: cols over gr bits (xor 4,8,16) ----
            float col_own;
            {
                float v4[4];
                #pragma unroll
                for (int j = 0; j < 4; ++j) {
                    float s = p0b ? cm[j] : cm[j + 4];
                    float k = p0b ? cm[j + 4] : cm[j];
                    v4[j] = fmaxf(k, __shfl_xor_sync(0xffffffffu, s, 4));
                }
                float v2[2];
                #pragma unroll
                for (int j = 0; j < 2; ++j) {
                    float s = p1b ? v4[j] : v4[j + 2];
                    float k = p1b ? v4[j + 2] : v4[j];
                    v2[j] = fmaxf(k, __shfl_xor_sync(0xffffffffu, s, 8));
                }
                float s = p2b ? v2[0] : v2[1];
                float k = p2b ? v2[1] : v2[0];
                col_own = fmaxf(k, __shfl_xor_sync(0xffffffffu, s, 16));
            }

            part[kk] = row_own + col_own;   // each lane owns 1 row + 1 col
        }

        // ---- Batched warp-sum of 8 partials (value-splitting reduction) ----
        float t4[4];
        {
            bool hi = (lane & 1);
            #pragma unroll
            for (int j = 0; j < 4; ++j) {
                float send = hi ? part[j] : part[j + 4];
                float keep = hi ? part[j + 4] : part[j];
                t4[j] = keep + __shfl_xor_sync(0xffffffffu, send, 1);
            }
        }
        float t2[2];
        {
            bool hi = (lane & 2);
            #pragma unroll
            for (int j = 0; j < 2; ++j) {
                float send = hi ? t4[j] : t4[j + 2];
                float keep = hi ? t4[j + 2] : t4[j];
                t2[j] = keep + __shfl_xor_sync(0xffffffffu, send, 2);
            }
        }
        float v;
        {
            bool hi = (lane & 4);
            float send = hi ? t2[0] : t2[1];
            float keep = hi ? t2[1] : t2[0];
            v = keep + __shfl_xor_sync(0xffffffffu, send, 4);
        }
        v += __shfl_xor_sync(0xffffffffu, v, 8);
        v += __shfl_xor_sync(0xffffffffu, v, 16);

        // lane (0..7) owns partial index j = 4*bit0 + 2*bit1 + bit2
        if (lane < 8) {
            int j = ((lane & 1) << 2) | (lane & 2) | ((lane >> 2) & 1);
            float res = 1.0f / (1.0f + __expf(v * -0.015625f));
            int k = k0 + b * NB + j;
            out0[k] = res;
            out1[k] = res;
        }
        __syncthreads();
    }
}

extern "C" void kernel_launch(void* const* d_in, const int* in_sizes, int n_in,
                              void* d_out, int out_size)
{
    const float* tgt = (const float*)d_in[0];   // [128, 768]
    const float* mem = (const float*)d_in[1];   // [2048, 768]
    float* out = (float*)d_out;                 // [2, 128, 2048]
    (void)in_sizes; (void)n_in; (void)out_size;

    cudaFuncSetAttribute(matcher_hmma,
                         cudaFuncAttributeMaxDynamicSharedMemorySize, SMEM_BYTES);
    matcher_hmma<<<1024, NTHR, SMEM_BYTES>>>(tgt, mem, out);
}

// round 11
// speedup vs baseline: 1.0168x; 1.0168x over previous
#include <cuda_runtime.h>
#include <cstdint>

#define NQ     128
#define NK     2048
#define D5     768
#define SEQ    32
#define ZD     24
#define NTHR   256
#define KCHUNK 32
#define NB     8
#define NBATCH (KCHUNK / NB)

// per-buffer u64s: NB rows * 2 ksteps * 32 s * 4 j
#define BUF_U64 (NB * 2 * 32 * 4)          // 2048
#define SMEM_BYTES (2 * BUF_U64 * 8)       // 32768

typedef unsigned long long ull;

__device__ __forceinline__ uint32_t pk(float lo, float hi) {
    uint32_t r; asm("cvt.rn.bf16x2.f32 %0, %1, %2;" : "=r"(r) : "f"(hi), "f"(lo));
    return r;
}

// ks0: full 4-reg A fragment, zero-init C (RZ)
__device__ __forceinline__ void mma16_z(float* c, const uint32_t* a, ull b) {
    uint32_t b0 = (uint32_t)b, b1 = (uint32_t)(b >> 32);
    asm volatile(
        "mma.sync.aligned.m16n8k16.row.col.f32.bf16.bf16.f32 "
        "{%0,%1,%2,%3}, {%4,%5,%6,%7}, {%8,%9}, {%10,%10,%10,%10};"
        : "=f"(c[0]), "=f"(c[1]), "=f"(c[2]), "=f"(c[3])
        : "r"(a[0]), "r"(a[1]), "r"(a[2]), "r"(a[3]), "r"(b0), "r"(b1), "f"(0.0f));
}
// ks1: A slots 2,3 are zeros (shared zero reg), accumulate
__device__ __forceinline__ void mma16_k1(float* c, uint32_t a0, uint32_t a1,
                                         uint32_t z, ull b) {
    uint32_t b0 = (uint32_t)b, b1 = (uint32_t)(b >> 32);
    asm volatile(
        "mma.sync.aligned.m16n8k16.row.col.f32.bf16.bf16.f32 "
        "{%0,%1,%2,%3}, {%4,%5,%6,%7}, {%8,%9}, {%0,%1,%2,%3};"
        : "+f"(c[0]), "+f"(c[1]), "+f"(c[2]), "+f"(c[3])
        : "r"(a0), "r"(a1), "r"(z), "r"(z), "r"(b0), "r"(b1));
}

// Stage NB memory rows as bf16, zipped so each B fragment is one LDS.64.
__device__ __forceinline__ void stage(ull* __restrict__ buf,
                                      const float* __restrict__ kbase, int tid) {
    int kk = tid >> 5, s = tid & 31;
    const float4* p = reinterpret_cast<const float4*>(kbase + kk * D5 + s * ZD);
    float4 x0 = p[0], x1 = p[1], x2 = p[2], x3 = p[3], x4 = p[4], x5 = p[5];
    uint32_t p0 = pk(x0.x, x0.y), p1 = pk(x0.z, x0.w);
    uint32_t p2 = pk(x1.x, x1.y), p3 = pk(x1.z, x1.w);
    uint32_t p4 = pk(x2.x, x2.y), p5 = pk(x2.z, x2.w);
    uint32_t p6 = pk(x3.x, x3.y), p7 = pk(x3.z, x3.w);
    uint32_t p8 = pk(x4.x, x4.y), p9 = pk(x4.z, x4.w);
    uint32_t pA = pk(x5.x, x5.y), pB = pk(x5.z, x5.w);
    ulonglong2* d0 = reinterpret_cast<ulonglong2*>(buf + ((size_t)(kk * 2) * 32 + s) * 4);
    d0[0] = make_ulonglong2((ull)p0 | ((ull)p4 << 32), (ull)p1 | ((ull)p5 << 32));
    d0[1] = make_ulonglong2((ull)p2 | ((ull)p6 << 32), (ull)p3 | ((ull)p7 << 32));
    ulonglong2* d1 = reinterpret_cast<ulonglong2*>(buf + ((size_t)(kk * 2 + 1) * 32 + s) * 4);
    d1[0] = make_ulonglong2((ull)p8, (ull)p9);
    d1[1] = make_ulonglong2((ull)pA, (ull)pB);
}

extern __shared__ ull sbuf[];

__global__ __launch_bounds__(NTHR, 4)
void matcher_hmma(const float* __restrict__ tgt,
                  const float* __restrict__ mem,
                  float* __restrict__ out)
{
    const int tid  = threadIdx.x;
    const int warp = tid >> 5;
    const int lane = tid & 31;
    const int gr   = lane >> 2;
    const int gc   = lane & 3;

    const int q0 = (blockIdx.x >> 6) * 8;       // 16 q-chunks
    const int k0 = (blockIdx.x & 63) * KCHUNK;  // 64 k-chunks
    const int q  = q0 + warp;

    // A fragments (bf16 pairs): ks0 full, ks1 only 2 useful regs + shared zero
    uint32_t afr0[2][4], afr1[2][2];
    const uint32_t zreg = 0u;
    {
        const float* a = tgt + (size_t)q * D5;
        #pragma unroll
        for (int mi = 0; mi < 2; ++mi) {
            int r = gr + 16 * mi;
            const float* r0 = a + r * ZD;
            const float* r1 = a + (r + 8) * ZD;
            afr0[mi][0] = pk(r0[2 * gc],      r0[2 * gc + 1]);
            afr0[mi][1] = pk(r1[2 * gc],      r1[2 * gc + 1]);
            afr0[mi][2] = pk(r0[2 * gc + 8],  r0[2 * gc + 9]);
            afr0[mi][3] = pk(r1[2 * gc + 8],  r1[2 * gc + 9]);
            afr1[mi][0] = pk(r0[2 * gc + 16], r0[2 * gc + 17]);
            afr1[mi][1] = pk(r1[2 * gc + 16], r1[2 * gc + 17]);
        }
    }

    float* __restrict__ out0 = out + (size_t)q * NK;
    float* __restrict__ out1 = out0 + (size_t)NQ * NK;

    stage(sbuf, mem + (size_t)k0 * D5, tid);
    __syncthreads();

    const int p0b = (lane >> 2) & 1;
    const int p1b = (lane >> 3) & 1;
    const int p2b = (lane >> 4) & 1;
    const int q0b = lane & 1;
    const int q1b = (lane >> 1) & 1;

    for (int b = 0; b < NBATCH; ++b) {
        ull* __restrict__ cur = sbuf + (size_t)(b & 1) * BUF_U64;
        if (b + 1 < NBATCH)
            stage(sbuf + (size_t)((b + 1) & 1) * BUF_U64,
                  mem + (size_t)(k0 + (b + 1) * NB) * D5, tid);

        float part[NB];

        #pragma unroll 1
        for (int kk = 0; kk < NB; ++kk) {
            const ull* __restrict__ bb = cur + (size_t)kk * 256;
            float acc[2][4][4];
            ull bf[4];
            // ks0
            #pragma unroll
            for (int ni = 0; ni < 4; ++ni)
                bf[ni] = bb[(gr + 8 * ni) * 4 + gc];
            #pragma unroll
            for (int mi = 0; mi < 2; ++mi)
                #pragma unroll
                for (int ni = 0; ni < 4; ++ni)
                    mma16_z(acc[mi][ni], afr0[mi], bf[ni]);
            // ks1 (reuse bf regs)
            #pragma unroll
            for (int ni = 0; ni < 4; ++ni)
                bf[ni] = bb[(32 + gr + 8 * ni) * 4 + gc];
            #pragma unroll
            for (int mi = 0; mi < 2; ++mi)
                #pragma unroll
                for (int ni = 0; ni < 4; ++ni)
                    mma16_k1(acc[mi][ni], afr1[mi][0], afr1[mi][1], zreg, bf[ni]);

            // ---- In-thread row maxes (4 slots), col maxes (8 slots) ----
            float rm[4];
            #pragma unroll
            for (int mi = 0; mi < 2; ++mi)
                #pragma unroll
                for (int h = 0; h < 2; ++h) {
                    float m = fmaxf(acc[mi][0][2 * h], acc[mi][0][2 * h + 1]);
                    #pragma unroll
                    for (int ni = 1; ni < 4; ++ni)
                        m = fmaxf(m, fmaxf(acc[mi][ni][2 * h], acc[mi][ni][2 * h + 1]));
                    rm[2 * mi + h] = m;
                }
            float cm[8];
            #pragma unroll
            for (int ni = 0; ni < 4; ++ni)
                #pragma unroll
                for (int p = 0; p < 2; ++p)
                    cm[ni * 2 + p] = fmaxf(fmaxf(acc[0][ni][p], acc[0][ni][p + 2]),
                                           fmaxf(acc[1][ni][p], acc[1][ni][p + 2]));

            // ---- Reduce-scatter: rows over gc bits (xor 1,2) ----
            float row_own;
            {
                float s0 = q0b ? rm[0] : rm[2], k0v = q0b ? rm[2] : rm[0];
                float s1 = q0b ? rm[1] : rm[3], k1v = q0b ? rm[3] : rm[1];
                float w0 = fmaxf(k0v, __shfl_xor_sync(0xffffffffu, s0, 1));
                float w1 = fmaxf(k1v, __shfl_xor_sync(0xffffffffu, s1, 1));
                float s2 = q1b ? w0 : w1, k2v = q1b ? w1 : w0;
                row_own = fmaxf(k2v, __shfl_xor_sync(0xffffffffu, s2, 2));
            }
            // ---- Reduce-scatter: cols over gr bits (xor 4,8,16) ----
            float col_own;
            {
                float v4[4];
                #pragma unroll
                for (int j = 0; j < 4; ++j) {
                    float s = p0b ? cm[j] : cm[j + 4];
                    float k = p0b ? cm[j + 4] : cm[j];
                    v4[j] = fmaxf(k, __shfl_xor_sync(0xffffffffu, s, 4));
                }
                float v2[2];
                #pragma unroll
                for (int j = 0; j < 2; ++j) {
                    float s = p1b ? v4[j] : v4[j + 2];
                    float k = p1b ? v4[j + 2] : v4[j];
                    v2[j] = fmaxf(k, __shfl_xor_sync(0xffffffffu, s, 8));
                }
                float s = p2b ? v2[0] : v2[1];
                float k = p2b ? v2[1] : v2[0];
                col_own = fmaxf(k, __shfl_xor_sync(0xffffffffu, s, 16));
            }

            part[kk] = row_own + col_own;   // each lane owns 1 row + 1 col
        }

        // ---- Batched warp-sum of 8 partials (value-splitting reduction) ----
        float t4[4];
        {
            bool hi = (lane & 1);
            #pragma unroll
            for (int j = 0; j < 4; ++j) {
                float send = hi ? part[j] : part[j + 4];
                float keep = hi ? part[j + 4] : part[j];
                t4[j] = keep + __shfl_xor_sync(0xffffffffu, send, 1);
            }
        }
        float t2[2];
        {
            bool hi = (lane & 2);
            #pragma unroll
            for (int j = 0; j < 2; ++j) {
                float send = hi ? t4[j] : t4[j + 2];
                float keep = hi ? t4[j + 2] : t4[j];
                t2[j] = keep + __shfl_xor_sync(0xffffffffu, send, 2);
            }
        }
        float v;
        {
            bool hi = (lane & 4);
            float send = hi ? t2[0] : t2[1];
            float keep = hi ? t2[1] : t2[0];
            v = keep + __shfl_xor_sync(0xffffffffu, send, 4);
        }
        v += __shfl_xor_sync(0xffffffffu, v, 8);
        v += __shfl_xor_sync(0xffffffffu, v, 16);

        // lane (0..7) owns partial index j = 4*bit0 + 2*bit1 + bit2
        if (lane < 8) {
            int j = ((lane & 1) << 2) | (lane & 2) | ((lane >> 2) & 1);
            float res = 1.0f / (1.0f + __expf(v * -0.015625f));
            int k = k0 + b * NB + j;
            out0[k] = res;
            out1[k] = res;
        }
        __syncthreads();
    }
}

extern "C" void kernel_launch(void* const* d_in, const int* in_sizes, int n_in,
                              void* d_out, int out_size)
{
    const float* tgt = (const float*)d_in[0];   // [128, 768]
    const float* mem = (const float*)d_in[1];   // [2048, 768]
    float* out = (float*)d_out;                 // [2, 128, 2048]
    (void)in_sizes; (void)n_in; (void)out_size;

    cudaFuncSetAttribute(matcher_hmma,
                         cudaFuncAttributeMaxDynamicSharedMemorySize, SMEM_BYTES);
    matcher_hmma<<<1024, NTHR, SMEM_BYTES>>>(tgt, mem, out);
}

// round 12
// speedup vs baseline: 1.1713x; 1.1519x over previous
#include <cuda_runtime.h>
#include <cuda_fp16.h>
#include <cstdint>

#define NQ     128
#define NK     2048
#define D5     768
#define SEQ    32
#define ZD     24
#define NTHR   256
#define KCHUNK 32
#define NB     8
#define NBATCH (KCHUNK / NB)

// per-buffer u64s: NB rows * 2 ksteps * 32 s * 4 j
#define BUF_U64 (NB * 2 * 32 * 4)          // 2048
#define SMEM_BYTES (2 * BUF_U64 * 8)       // 32768

typedef unsigned long long ull;

// pack two floats -> f16x2 (lo, hi)
__device__ __forceinline__ uint32_t pkh(float lo, float hi) {
    __half2 h = __floats2half2_rn(lo, hi);
    return *reinterpret_cast<uint32_t*>(&h);
}
// packed f16x2 max (HMNMX2)
__device__ __forceinline__ uint32_t hmax2u(uint32_t a, uint32_t b) {
    uint32_t d; asm("max.f16x2 %0, %1, %2;" : "=r"(d) : "r"(a), "r"(b));
    return d;
}
__device__ __forceinline__ float2 h2f2(uint32_t p) {
    __half2 h = *reinterpret_cast<__half2*>(&p);
    return __half22float2(h);
}

// f16 MMA, f16 accumulator (D/C = 2 regs), zero-init C
__device__ __forceinline__ void hmma_z(uint32_t* c, const uint32_t* a, ull b) {
    uint32_t b0 = (uint32_t)b, b1 = (uint32_t)(b >> 32);
    asm volatile(
        "mma.sync.aligned.m16n8k16.row.col.f16.f16.f16.f16 "
        "{%0,%1}, {%2,%3,%4,%5}, {%6,%7}, {%8,%8};"
        : "=r"(c[0]), "=r"(c[1])
        : "r"(a[0]), "r"(a[1]), "r"(a[2]), "r"(a[3]), "r"(b0), "r"(b1), "r"(0u));
}
// accumulate; A slots 2,3 zero (ks1: k=16..23 data only in a0,a1)
__device__ __forceinline__ void hmma_k1(uint32_t* c, uint32_t a0, uint32_t a1,
                                        uint32_t z, ull b) {
    uint32_t b0 = (uint32_t)b, b1 = (uint32_t)(b >> 32);
    asm volatile(
        "mma.sync.aligned.m16n8k16.row.col.f16.f16.f16.f16 "
        "{%0,%1}, {%2,%3,%4,%5}, {%6,%7}, {%0,%1};"
        : "+r"(c[0]), "+r"(c[1])
        : "r"(a0), "r"(a1), "r"(z), "r"(z), "r"(b0), "r"(b1));
}

// Stage NB memory rows as f16, zipped so each B fragment is one LDS.64.
__device__ __forceinline__ void stage(ull* __restrict__ buf,
                                      const float* __restrict__ kbase, int tid) {
    int kk = tid >> 5, s = tid & 31;
    const float4* p = reinterpret_cast<const float4*>(kbase + kk * D5 + s * ZD);
    float4 x0 = p[0], x1 = p[1], x2 = p[2], x3 = p[3], x4 = p[4], x5 = p[5];
    uint32_t p0 = pkh(x0.x, x0.y), p1 = pkh(x0.z, x0.w);
    uint32_t p2 = pkh(x1.x, x1.y), p3 = pkh(x1.z, x1.w);
    uint32_t p4 = pkh(x2.x, x2.y), p5 = pkh(x2.z, x2.w);
    uint32_t p6 = pkh(x3.x, x3.y), p7 = pkh(x3.z, x3.w);
    uint32_t p8 = pkh(x4.x, x4.y), p9 = pkh(x4.z, x4.w);
    uint32_t pA = pkh(x5.x, x5.y), pB = pkh(x5.z, x5.w);
    ulonglong2* d0 = reinterpret_cast<ulonglong2*>(buf + ((size_t)(kk * 2) * 32 + s) * 4);
    d0[0] = make_ulonglong2((ull)p0 | ((ull)p4 << 32), (ull)p1 | ((ull)p5 << 32));
    d0[1] = make_ulonglong2((ull)p2 | ((ull)p6 << 32), (ull)p3 | ((ull)p7 << 32));
    ulonglong2* d1 = reinterpret_cast<ulonglong2*>(buf + ((size_t)(kk * 2 + 1) * 32 + s) * 4);
    d1[0] = make_ulonglong2((ull)p8, (ull)p9);
    d1[1] = make_ulonglong2((ull)pA, (ull)pB);
}

extern __shared__ ull sbuf[];

__global__ __launch_bounds__(NTHR, 4)
void matcher_hmma(const float* __restrict__ tgt,
                  const float* __restrict__ mem,
                  float* __restrict__ out)
{
    const int tid  = threadIdx.x;
    const int warp = tid >> 5;
    const int lane = tid & 31;
    const int gr   = lane >> 2;
    const int gc   = lane & 3;

    const int q0 = (blockIdx.x >> 6) * 8;       // 16 q-chunks
    const int k0 = (blockIdx.x & 63) * KCHUNK;  // 64 k-chunks
    const int q  = q0 + warp;

    // A fragments (f16 pairs): ks0 full 4 regs, ks1 2 useful regs + shared zero
    uint32_t afr0[2][4], afr1[2][2];
    const uint32_t zreg = 0u;
    {
        const float* a = tgt + (size_t)q * D5;
        #pragma unroll
        for (int mi = 0; mi < 2; ++mi) {
            int r = gr + 16 * mi;
            const float* r0 = a + r * ZD;
            const float* r1 = a + (r + 8) * ZD;
            afr0[mi][0] = pkh(r0[2 * gc],      r0[2 * gc + 1]);
            afr0[mi][1] = pkh(r1[2 * gc],      r1[2 * gc + 1]);
            afr0[mi][2] = pkh(r0[2 * gc + 8],  r0[2 * gc + 9]);
            afr0[mi][3] = pkh(r1[2 * gc + 8],  r1[2 * gc + 9]);
            afr1[mi][0] = pkh(r0[2 * gc + 16], r0[2 * gc + 17]);
            afr1[mi][1] = pkh(r1[2 * gc + 16], r1[2 * gc + 17]);
        }
    }

    float* __restrict__ out0 = out + (size_t)q * NK;
    float* __restrict__ out1 = out0 + (size_t)NQ * NK;

    stage(sbuf, mem + (size_t)k0 * D5, tid);
    __syncthreads();

    const int p0b = (lane >> 2) & 1;   // gr bit0 (xor 4)
    const int p1b = (lane >> 3) & 1;   // gr bit1 (xor 8)
    const int q0b = lane & 1;          // gc bit0 (xor 1)
    const int q1b = (lane >> 1) & 1;   // gc bit1 (xor 2)

    for (int b = 0; b < NBATCH; ++b) {
        ull* __restrict__ cur = sbuf + (size_t)(b & 1) * BUF_U64;
        if (b + 1 < NBATCH)
            stage(sbuf + (size_t)((b + 1) & 1) * BUF_U64,
                  mem + (size_t)(k0 + (b + 1) * NB) * D5, tid);

        float part[NB];

        #pragma unroll 1
        for (int kk = 0; kk < NB; ++kk) {
            const ull* __restrict__ bb = cur + (size_t)kk * 256;
            uint32_t acc[2][4][2];     // [mi][ni][j]: j = row gr+8j, cols (2gc,2gc+1) packed
            ull bf[4];
            #pragma unroll
            for (int ni = 0; ni < 4; ++ni)
                bf[ni] = bb[(gr + 8 * ni) * 4 + gc];
            #pragma unroll
            for (int mi = 0; mi < 2; ++mi)
                #pragma unroll
                for (int ni = 0; ni < 4; ++ni)
                    hmma_z(acc[mi][ni], afr0[mi], bf[ni]);
            #pragma unroll
            for (int ni = 0; ni < 4; ++ni)
                bf[ni] = bb[(32 + gr + 8 * ni) * 4 + gc];
            #pragma unroll
            for (int mi = 0; mi < 2; ++mi)
                #pragma unroll
                for (int ni = 0; ni < 4; ++ni)
                    hmma_k1(acc[mi][ni], afr1[mi][0], afr1[mi][1], zreg, bf[ni]);

            // ---- In-thread packed row maxes over ni: 4 slots (row gr+8j+16mi) ----
            uint32_t rm[4];
            #pragma unroll
            for (int mi = 0; mi < 2; ++mi)
                #pragma unroll
                for (int j = 0; j < 2; ++j) {
                    uint32_t m = hmax2u(acc[mi][0][j], acc[mi][1][j]);
                    m = hmax2u(m, acc[mi][2][j]);
                    rm[2 * mi + j] = hmax2u(m, acc[mi][3][j]);
                }
            // ---- In-thread packed col maxes over rows (mi,j): 4 slots (ni) ----
            uint32_t cm[4];
            #pragma unroll
            for (int ni = 0; ni < 4; ++ni) {
                uint32_t m = hmax2u(acc[0][ni][0], acc[0][ni][1]);
                m = hmax2u(m, acc[1][ni][0]);
                cm[ni] = hmax2u(m, acc[1][ni][1]);
            }

            // ---- Rows: reduce-scatter over gc bits (xor 1, 2), packed ----
            float rowf;
            {
                uint32_t s0 = q0b ? rm[0] : rm[2], k0v = q0b ? rm[2] : rm[0];
                uint32_t s1 = q0b ? rm[1] : rm[3], k1v = q0b ? rm[3] : rm[1];
                uint32_t w0 = hmax2u(k0v, __shfl_xor_sync(0xffffffffu, s0, 1));
                uint32_t w1 = hmax2u(k1v, __shfl_xor_sync(0xffffffffu, s1, 1));
                uint32_t s2 = q1b ? w0 : w1, k2v = q1b ? w1 : w0;
                uint32_t ro = hmax2u(k2v, __shfl_xor_sync(0xffffffffu, s2, 2));
                float2 rf = h2f2(ro);
                rowf = fmaxf(rf.x, rf.y);    // merge even/odd col halves
            }
            // ---- Cols: reduce-scatter over gr bits (xor 4, 8) + butterfly (16) ----
            float colf;
            {
                uint32_t v4[2];
                #pragma unroll
                for (int j = 0; j < 2; ++j) {
                    uint32_t s = p0b ? cm[j] : cm[j + 2];
                    uint32_t k = p0b ? cm[j + 2] : cm[j];
                    v4[j] = hmax2u(k, __shfl_xor_sync(0xffffffffu, s, 4));
                }
                uint32_t s = p1b ? v4[0] : v4[1];
                uint32_t k = p1b ? v4[1] : v4[0];
                uint32_t v2 = hmax2u(k, __shfl_xor_sync(0xffffffffu, s, 8));
                uint32_t cp = hmax2u(v2, __shfl_xor_sync(0xffffffffu, v2, 16));
                float2 cf = h2f2(cp);
                colf = 0.5f * (cf.x + cf.y); // each packed value replicated in 2 lanes
            }

            part[kk] = rowf + colf;
        }

        // ---- Batched warp-sum of 8 partials (value-splitting reduction) ----
        float t4[4];
        {
            bool hi = (lane & 1);
            #pragma unroll
            for (int j = 0; j < 4; ++j) {
                float send = hi ? part[j] : part[j + 4];
                float keep = hi ? part[j + 4] : part[j];
                t4[j] = keep + __shfl_xor_sync(0xffffffffu, send, 1);
            }
        }
        float t2[2];
        {
            bool hi = (lane & 2);
            #pragma unroll
            for (int j = 0; j < 2; ++j) {
                float send = hi ? t4[j] : t4[j + 2];
                float keep = hi ? t4[j + 2] : t4[j];
                t2[j] = keep + __shfl_xor_sync(0xffffffffu, send, 2);
            }
        }
        float v;
        {
            bool hi = (lane & 4);
            float send = hi ? t2[0] : t2[1];
            float keep = hi ? t2[1] : t2[0];
            v = keep + __shfl_xor_sync(0xffffffffu, send, 4);
        }
        v += __shfl_xor_sync(0xffffffffu, v, 8);
        v += __shfl_xor_sync(0xffffffffu, v, 16);

        // lane (0..7) owns partial index j = 4*bit0 + 2*bit1 + bit2
        if (lane < 8) {
            int j = ((lane & 1) << 2) | (lane & 2) | ((lane >> 2) & 1);
            float res = 1.0f / (1.0f + __expf(v * -0.015625f));
            int k = k0 + b * NB + j;
            out0[k] = res;
            out1[k] = res;
        }
        __syncthreads();
    }
}

extern "C" void kernel_launch(void* const* d_in, const int* in_sizes, int n_in,
                              void* d_out, int out_size)
{
    const float* tgt = (const float*)d_in[0];   // [128, 768]
    const float* mem = (const float*)d_in[1];   // [2048, 768]
    float* out = (float*)d_out;                 // [2, 128, 2048]
    (void)in_sizes; (void)n_in; (void)out_size;

    cudaFuncSetAttribute(matcher_hmma,
                         cudaFuncAttributeMaxDynamicSharedMemorySize, SMEM_BYTES);
    matcher_hmma<<<1024, NTHR, SMEM_BYTES>>>(tgt, mem, out);
}

// round 13
// speedup vs baseline: 1.2340x; 1.0535x over previous
#include <cuda_runtime.h>
#include <cuda_fp16.h>
#include <cstdint>

#define NQ     128
#define NK     2048
#define D5     768
#define SEQ    32
#define ZD     24
#define NTHR   256
#define KCHUNK 32
#define NB     8
#define NBATCH (KCHUNK / NB)

// per-buffer: ks0 = NB*32 rows * 4 u64 (8KB), ks1 = NB*32 rows * 4 u32 (4KB)
#define BUF0_U64 (NB * 32 * 4)             // 1024 u64
#define BUF1_U32 (NB * 32 * 4)             // 1024 u32
#define BUF_BYTES (BUF0_U64 * 8 + BUF1_U32 * 4)   // 12288
#define SMEM_BYTES (2 * BUF_BYTES)                 // 24576

typedef unsigned long long ull;

// pack two floats -> f16x2 (lo, hi)
__device__ __forceinline__ uint32_t pkh(float lo, float hi) {
    __half2 h = __floats2half2_rn(lo, hi);
    return *reinterpret_cast<uint32_t*>(&h);
}
// packed f16x2 max (HMNMX2)
__device__ __forceinline__ uint32_t hmax2u(uint32_t a, uint32_t b) {
    uint32_t d; asm("max.f16x2 %0, %1, %2;" : "=r"(d) : "r"(a), "r"(b));
    return d;
}
__device__ __forceinline__ float2 h2f2(uint32_t p) {
    __half2 h = *reinterpret_cast<__half2*>(&p);
    return __half22float2(h);
}

// K=16 f16 MMA, f16 accumulator, zero-init C
__device__ __forceinline__ void hmma_z(uint32_t* c, const uint32_t* a, ull b) {
    uint32_t b0 = (uint32_t)b, b1 = (uint32_t)(b >> 32);
    asm volatile(
        "mma.sync.aligned.m16n8k16.row.col.f16.f16.f16.f16 "
        "{%0,%1}, {%2,%3,%4,%5}, {%6,%7}, {%8,%8};"
        : "=r"(c[0]), "=r"(c[1])
        : "r"(a[0]), "r"(a[1]), "r"(a[2]), "r"(a[3]), "r"(b0), "r"(b1), "r"(0u));
}
// K=8 f16 MMA (exact fit for K=16..23), accumulate
__device__ __forceinline__ void hmma_k8(uint32_t* c, uint32_t a0, uint32_t a1,
                                        uint32_t b0) {
    asm volatile(
        "mma.sync.aligned.m16n8k8.row.col.f16.f16.f16.f16 "
        "{%0,%1}, {%2,%3}, {%4}, {%0,%1};"
        : "+r"(c[0]), "+r"(c[1])
        : "r"(a0), "r"(a1), "r"(b0));
}

// Stage NB memory rows as f16. ks0: zipped u64 pairs (one LDS.64 per B frag).
// ks1: plain u32 (one LDS.32 per k8 B frag).
__device__ __forceinline__ void stage(char* __restrict__ base,
                                      const float* __restrict__ kbase, int tid) {
    ull*      b0 = reinterpret_cast<ull*>(base);
    uint32_t* b1 = reinterpret_cast<uint32_t*>(base + BUF0_U64 * 8);
    int kk = tid >> 5, s = tid & 31;
    const float4* p = reinterpret_cast<const float4*>(kbase + kk * D5 + s * ZD);
    float4 x0 = p[0], x1 = p[1], x2 = p[2], x3 = p[3], x4 = p[4], x5 = p[5];
    uint32_t p0 = pkh(x0.x, x0.y), p1 = pkh(x0.z, x0.w);
    uint32_t p2 = pkh(x1.x, x1.y), p3 = pkh(x1.z, x1.w);
    uint32_t p4 = pkh(x2.x, x2.y), p5 = pkh(x2.z, x2.w);
    uint32_t p6 = pkh(x3.x, x3.y), p7 = pkh(x3.z, x3.w);
    uint32_t p8 = pkh(x4.x, x4.y), p9 = pkh(x4.z, x4.w);
    uint32_t pA = pkh(x5.x, x5.y), pB = pkh(x5.z, x5.w);
    ulonglong2* d0 = reinterpret_cast<ulonglong2*>(b0 + ((size_t)kk * 32 + s) * 4);
    d0[0] = make_ulonglong2((ull)p0 | ((ull)p4 << 32), (ull)p1 | ((ull)p5 << 32));
    d0[1] = make_ulonglong2((ull)p2 | ((ull)p6 << 32), (ull)p3 | ((ull)p7 << 32));
    uint4* d1 = reinterpret_cast<uint4*>(b1 + ((size_t)kk * 32 + s) * 4);
    *d1 = make_uint4(p8, p9, pA, pB);
}

extern __shared__ char sbuf[];

__global__ __launch_bounds__(NTHR, 4)
void matcher_hmma(const float* __restrict__ tgt,
                  const float* __restrict__ mem,
                  float* __restrict__ out)
{
    const int tid  = threadIdx.x;
    const int warp = tid >> 5;
    const int lane = tid & 31;
    const int gr   = lane >> 2;
    const int gc   = lane & 3;

    const int q0 = (blockIdx.x >> 6) * 8;       // 16 q-chunks
    const int k0 = (blockIdx.x & 63) * KCHUNK;  // 64 k-chunks
    const int q  = q0 + warp;

    // A fragments (f16 pairs): ks0 full 4 regs (k16), ks1 2 regs (k8)
    uint32_t afr0[2][4], afr1[2][2];
    {
        const float* a = tgt + (size_t)q * D5;
        #pragma unroll
        for (int mi = 0; mi < 2; ++mi) {
            int r = gr + 16 * mi;
            const float* r0 = a + r * ZD;
            const float* r1 = a + (r + 8) * ZD;
            afr0[mi][0] = pkh(r0[2 * gc],      r0[2 * gc + 1]);
            afr0[mi][1] = pkh(r1[2 * gc],      r1[2 * gc + 1]);
            afr0[mi][2] = pkh(r0[2 * gc + 8],  r0[2 * gc + 9]);
            afr0[mi][3] = pkh(r1[2 * gc + 8],  r1[2 * gc + 9]);
            afr1[mi][0] = pkh(r0[2 * gc + 16], r0[2 * gc + 17]);
            afr1[mi][1] = pkh(r1[2 * gc + 16], r1[2 * gc + 17]);
        }
    }

    float* __restrict__ out0 = out + (size_t)q * NK;
    float* __restrict__ out1 = out0 + (size_t)NQ * NK;

    stage(sbuf, mem + (size_t)k0 * D5, tid);
    __syncthreads();

    const int p0b = (lane >> 2) & 1;   // gr bit0 (xor 4)
    const int p1b = (lane >> 3) & 1;   // gr bit1 (xor 8)
    const int q0b = lane & 1;          // gc bit0 (xor 1)
    const int q1b = (lane >> 1) & 1;   // gc bit1 (xor 2)

    for (int b = 0; b < NBATCH; ++b) {
        char* __restrict__ curbase = sbuf + (size_t)(b & 1) * BUF_BYTES;
        const ull*      cur0 = reinterpret_cast<const ull*>(curbase);
        const uint32_t* cur1 = reinterpret_cast<const uint32_t*>(curbase + BUF0_U64 * 8);
        if (b + 1 < NBATCH)
            stage(sbuf + (size_t)((b + 1) & 1) * BUF_BYTES,
                  mem + (size_t)(k0 + (b + 1) * NB) * D5, tid);

        float part[NB];

        #pragma unroll 1
        for (int kk = 0; kk < NB; ++kk) {
            const ull*      bb0 = cur0 + (size_t)kk * 128;
            const uint32_t* bb1 = cur1 + (size_t)kk * 128;
            uint32_t acc[2][4][2];     // [mi][ni][j]: j = row gr+8j, cols (2gc,2gc+1) packed
            // ks0 (K=0..15), m16n8k16
            ull bf[4];
            #pragma unroll
            for (int ni = 0; ni < 4; ++ni)
                bf[ni] = bb0[(gr + 8 * ni) * 4 + gc];
            #pragma unroll
            for (int mi = 0; mi < 2; ++mi)
                #pragma unroll
                for (int ni = 0; ni < 4; ++ni)
                    hmma_z(acc[mi][ni], afr0[mi], bf[ni]);
            // ks1 (K=16..23), m16n8k8 — exact fit, no zero padding
            uint32_t bh[4];
            #pragma unroll
            for (int ni = 0; ni < 4; ++ni)
                bh[ni] = bb1[(gr + 8 * ni) * 4 + gc];
            #pragma unroll
            for (int mi = 0; mi < 2; ++mi)
                #pragma unroll
                for (int ni = 0; ni < 4; ++ni)
                    hmma_k8(acc[mi][ni], afr1[mi][0], afr1[mi][1], bh[ni]);

            // ---- In-thread packed row maxes over ni: 4 slots (row gr+8j+16mi) ----
            uint32_t rm[4];
            #pragma unroll
            for (int mi = 0; mi < 2; ++mi)
                #pragma unroll
                for (int j = 0; j < 2; ++j) {
                    uint32_t m = hmax2u(acc[mi][0][j], acc[mi][1][j]);
                    m = hmax2u(m, acc[mi][2][j]);
                    rm[2 * mi + j] = hmax2u(m, acc[mi][3][j]);
                }
            // ---- In-thread packed col maxes over rows (mi,j): 4 slots (ni) ----
            uint32_t cm[4];
            #pragma unroll
            for (int ni = 0; ni < 4; ++ni) {
                uint32_t m = hmax2u(acc[0][ni][0], acc[0][ni][1]);
                m = hmax2u(m, acc[1][ni][0]);
                cm[ni] = hmax2u(m, acc[1][ni][1]);
            }

            // ---- Rows: reduce-scatter over gc bits (xor 1, 2), packed ----
            float rowf;
            {
                uint32_t s0 = q0b ? rm[0] : rm[2], k0v = q0b ? rm[2] : rm[0];
                uint32_t s1 = q0b ? rm[1] : rm[3], k1v = q0b ? rm[3] : rm[1];
                uint32_t w0 = hmax2u(k0v, __shfl_xor_sync(0xffffffffu, s0, 1));
                uint32_t w1 = hmax2u(k1v, __shfl_xor_sync(0xffffffffu, s1, 1));
                uint32_t s2 = q1b ? w0 : w1, k2v = q1b ? w1 : w0;
                uint32_t ro = hmax2u(k2v, __shfl_xor_sync(0xffffffffu, s2, 2));
                float2 rf = h2f2(ro);
                rowf = fmaxf(rf.x, rf.y);    // merge even/odd col halves
            }
            // ---- Cols: reduce-scatter over gr bits (xor 4, 8) + butterfly (16) ----
            float colf;
            {
                uint32_t v4[2];
                #pragma unroll
                for (int j = 0; j < 2; ++j) {
                    uint32_t s = p0b ? cm[j] : cm[j + 2];
                    uint32_t k = p0b ? cm[j + 2] : cm[j];
                    v4[j] = hmax2u(k, __shfl_xor_sync(0xffffffffu, s, 4));
                }
                uint32_t s = p1b ? v4[0] : v4[1];
                uint32_t k = p1b ? v4[1] : v4[0];
                uint32_t v2 = hmax2u(k, __shfl_xor_sync(0xffffffffu, s, 8));
                uint32_t cp = hmax2u(v2, __shfl_xor_sync(0xffffffffu, v2, 16));
                float2 cf = h2f2(cp);
                colf = 0.5f * (cf.x + cf.y); // each packed value replicated in 2 lanes
            }

            part[kk] = rowf + colf;
        }

        // ---- Batched warp-sum of 8 partials (value-splitting reduction) ----
        float t4[4];
        {
            bool hi = (lane & 1);
            #pragma unroll
            for (int j = 0; j < 4; ++j) {
                float send = hi ? part[j] : part[j + 4];
                float keep = hi ? part[j + 4] : part[j];
                t4[j] = keep + __shfl_xor_sync(0xffffffffu, send, 1);
            }
        }
        float t2[2];
        {
            bool hi = (lane & 2);
            #pragma unroll
            for (int j = 0; j < 2; ++j) {
                float send = hi ? t4[j] : t4[j + 2];
                float keep = hi ? t4[j + 2] : t4[j];
                t2[j] = keep + __shfl_xor_sync(0xffffffffu, send, 2);
            }
        }
        float v;
        {
            bool hi = (lane & 4);
            float send = hi ? t2[0] : t2[1];
            float keep = hi ? t2[1] : t2[0];
            v = keep + __shfl_xor_sync(0xffffffffu, send, 4);
        }
        v += __shfl_xor_sync(0xffffffffu, v, 8);
        v += __shfl_xor_sync(0xffffffffu, v, 16);

        // lane (0..7) owns partial index j = 4*bit0 + 2*bit1 + bit2
        if (lane < 8) {
            int j = ((lane & 1) << 2) | (lane & 2) | ((lane >> 2) & 1);
            float res = 1.0f / (1.0f + __expf(v * -0.015625f));
            int k = k0 + b * NB + j;
            out0[k] = res;
            out1[k] = res;
        }
        __syncthreads();
    }
}

extern "C" void kernel_launch(void* const* d_in, const int* in_sizes, int n_in,
                              void* d_out, int out_size)
{
    const float* tgt = (const float*)d_in[0];   // [128, 768]
    const float* mem = (const float*)d_in[1];   // [2048, 768]
    float* out = (float*)d_out;                 // [2, 128, 2048]
    (void)in_sizes; (void)n_in; (void)out_size;

    cudaFuncSetAttribute(matcher_hmma,
                         cudaFuncAttributeMaxDynamicSharedMemorySize, SMEM_BYTES);
    matcher_hmma<<<1024, NTHR, SMEM_BYTES>>>(tgt, mem, out);
}

// round 14
// speedup vs baseline: 1.2381x; 1.0033x over previous
#include <cuda_runtime.h>
#include <cuda_fp16.h>
#include <cstdint>

#define NQ     128
#define NK     2048
#define D5     768
#define SEQ    32
#define ZD     24
#define NTHR   256
#define KCHUNK 32

// Single staged region: ks0 = 32k * 32s * 4 u64 (32KB), ks1 = 32k * 32s * 4 u32 (16KB)
#define B0_U64 (KCHUNK * 32 * 4)            // 4096 u64
#define B1_U32 (KCHUNK * 32 * 4)            // 4096 u32
#define SMEM_BYTES (B0_U64 * 8 + B1_U32 * 4)  // 49152

typedef unsigned long long ull;

__device__ __forceinline__ uint32_t pkh(float lo, float hi) {
    __half2 h = __floats2half2_rn(lo, hi);
    return *reinterpret_cast<uint32_t*>(&h);
}
__device__ __forceinline__ uint32_t hmax2u(uint32_t a, uint32_t b) {
    uint32_t d; asm("max.f16x2 %0, %1, %2;" : "=r"(d) : "r"(a), "r"(b));
    return d;
}
__device__ __forceinline__ float2 h2f2(uint32_t p) {
    __half2 h = *reinterpret_cast<__half2*>(&p);
    return __half22float2(h);
}

__device__ __forceinline__ void hmma_z(uint32_t* c, const uint32_t* a, ull b) {
    uint32_t b0 = (uint32_t)b, b1 = (uint32_t)(b >> 32);
    asm volatile(
        "mma.sync.aligned.m16n8k16.row.col.f16.f16.f16.f16 "
        "{%0,%1}, {%2,%3,%4,%5}, {%6,%7}, {%8,%8};"
        : "=r"(c[0]), "=r"(c[1])
        : "r"(a[0]), "r"(a[1]), "r"(a[2]), "r"(a[3]), "r"(b0), "r"(b1), "r"(0u));
}
__device__ __forceinline__ void hmma_k8(uint32_t* c, uint32_t a0, uint32_t a1,
                                        uint32_t b0) {
    asm volatile(
        "mma.sync.aligned.m16n8k8.row.col.f16.f16.f16.f16 "
        "{%0,%1}, {%2,%3}, {%4}, {%0,%1};"
        : "+r"(c[0]), "+r"(c[1])
        : "r"(a0), "r"(a1), "r"(b0));
}

extern __shared__ char sbuf[];

__global__ __launch_bounds__(NTHR, 4)
void matcher_hmma(const float* __restrict__ tgt,
                  const float* __restrict__ mem,
                  float* __restrict__ out)
{
    const int tid  = threadIdx.x;
    const int warp = tid >> 5;
    const int lane = tid & 31;
    const int gr   = lane >> 2;
    const int gc   = lane & 3;

    const int q0 = (blockIdx.x >> 6) * 8;       // 16 q-chunks
    const int k0 = (blockIdx.x & 63) * KCHUNK;  // 64 k-chunks
    const int q  = q0 + warp;

    ull*      sb0 = reinterpret_cast<ull*>(sbuf);
    uint32_t* sb1 = reinterpret_cast<uint32_t*>(sbuf + B0_U64 * 8);

    // ---- Stage ALL 32 k-rows up front (4 tasks per thread) ----
    #pragma unroll
    for (int i = 0; i < 4; ++i) {
        int task = tid + i * NTHR;              // 0..1023
        int kk = task >> 5, s = task & 31;
        const float4* p = reinterpret_cast<const float4*>(
            mem + (size_t)(k0 + kk) * D5 + s * ZD);
        float4 x0 = p[0], x1 = p[1], x2 = p[2], x3 = p[3], x4 = p[4], x5 = p[5];
        uint32_t p0 = pkh(x0.x, x0.y), p1 = pkh(x0.z, x0.w);
        uint32_t p2 = pkh(x1.x, x1.y), p3 = pkh(x1.z, x1.w);
        uint32_t p4 = pkh(x2.x, x2.y), p5 = pkh(x2.z, x2.w);
        uint32_t p6 = pkh(x3.x, x3.y), p7 = pkh(x3.z, x3.w);
        uint32_t p8 = pkh(x4.x, x4.y), p9 = pkh(x4.z, x4.w);
        uint32_t pA = pkh(x5.x, x5.y), pB = pkh(x5.z, x5.w);
        ulonglong2* d0 = reinterpret_cast<ulonglong2*>(sb0 + ((size_t)kk * 32 + s) * 4);
        d0[0] = make_ulonglong2((ull)p0 | ((ull)p4 << 32), (ull)p1 | ((ull)p5 << 32));
        d0[1] = make_ulonglong2((ull)p2 | ((ull)p6 << 32), (ull)p3 | ((ull)p7 << 32));
        uint4* d1 = reinterpret_cast<uint4*>(sb1 + ((size_t)kk * 32 + s) * 4);
        *d1 = make_uint4(p8, p9, pA, pB);
    }

    // A fragments (f16 pairs): ks0 full 4 regs (k16), ks1 2 regs (k8)
    uint32_t afr0[2][4], afr1[2][2];
    {
        const float* a = tgt + (size_t)q * D5;
        #pragma unroll
        for (int mi = 0; mi < 2; ++mi) {
            int r = gr + 16 * mi;
            const float* r0 = a + r * ZD;
            const float* r1 = a + (r + 8) * ZD;
            afr0[mi][0] = pkh(r0[2 * gc],      r0[2 * gc + 1]);
            afr0[mi][1] = pkh(r1[2 * gc],      r1[2 * gc + 1]);
            afr0[mi][2] = pkh(r0[2 * gc + 8],  r0[2 * gc + 9]);
            afr0[mi][3] = pkh(r1[2 * gc + 8],  r1[2 * gc + 9]);
            afr1[mi][0] = pkh(r0[2 * gc + 16], r0[2 * gc + 17]);
            afr1[mi][1] = pkh(r1[2 * gc + 16], r1[2 * gc + 17]);
        }
    }

    float* __restrict__ out0 = out + (size_t)q * NK;
    float* __restrict__ out1 = out0 + (size_t)NQ * NK;

    __syncthreads();   // the ONLY sync — after this, warps run free and drift out of phase

    const int p0b = (lane >> 2) & 1;   // gr bit0 (xor 4)
    const int p1b = (lane >> 3) & 1;   // gr bit1 (xor 8)
    const int q0b = lane & 1;          // gc bit0 (xor 1)
    const int q1b = (lane >> 1) & 1;   // gc bit1 (xor 2)

    #pragma unroll 1
    for (int g = 0; g < KCHUNK / 8; ++g) {
        float part[8];

        #pragma unroll 1
        for (int kj = 0; kj < 8; ++kj) {
            const int kk = g * 8 + kj;
            const ull*      bb0 = sb0 + (size_t)kk * 128;
            const uint32_t* bb1 = sb1 + (size_t)kk * 128;
            uint32_t acc[2][4][2];     // [mi][ni][j]: row gr+8j, cols (2gc,2gc+1) packed
            ull bf[4];
            #pragma unroll
            for (int ni = 0; ni < 4; ++ni)
                bf[ni] = bb0[(gr + 8 * ni) * 4 + gc];
            #pragma unroll
            for (int mi = 0; mi < 2; ++mi)
                #pragma unroll
                for (int ni = 0; ni < 4; ++ni)
                    hmma_z(acc[mi][ni], afr0[mi], bf[ni]);
            uint32_t bh[4];
            #pragma unroll
            for (int ni = 0; ni < 4; ++ni)
                bh[ni] = bb1[(gr + 8 * ni) * 4 + gc];
            #pragma unroll
            for (int mi = 0; mi < 2; ++mi)
                #pragma unroll
                for (int ni = 0; ni < 4; ++ni)
                    hmma_k8(acc[mi][ni], afr1[mi][0], afr1[mi][1], bh[ni]);

            // ---- In-thread packed row maxes over ni ----
            uint32_t rm[4];
            #pragma unroll
            for (int mi = 0; mi < 2; ++mi)
                #pragma unroll
                for (int j = 0; j < 2; ++j) {
                    uint32_t m = hmax2u(acc[mi][0][j], acc[mi][1][j]);
                    m = hmax2u(m, acc[mi][2][j]);
                    rm[2 * mi + j] = hmax2u(m, acc[mi][3][j]);
                }
            // ---- In-thread packed col maxes over rows ----
            uint32_t cm[4];
            #pragma unroll
            for (int ni = 0; ni < 4; ++ni) {
                uint32_t m = hmax2u(acc[0][ni][0], acc[0][ni][1]);
                m = hmax2u(m, acc[1][ni][0]);
                cm[ni] = hmax2u(m, acc[1][ni][1]);
            }

            // ---- Rows: reduce-scatter over gc bits (xor 1, 2), packed ----
            float rowf;
            {
                uint32_t s0 = q0b ? rm[0] : rm[2], k0v = q0b ? rm[2] : rm[0];
                uint32_t s1 = q0b ? rm[1] : rm[3], k1v = q0b ? rm[3] : rm[1];
                uint32_t w0 = hmax2u(k0v, __shfl_xor_sync(0xffffffffu, s0, 1));
                uint32_t w1 = hmax2u(k1v, __shfl_xor_sync(0xffffffffu, s1, 1));
                uint32_t s2 = q1b ? w0 : w1, k2v = q1b ? w1 : w0;
                uint32_t ro = hmax2u(k2v, __shfl_xor_sync(0xffffffffu, s2, 2));
                float2 rf = h2f2(ro);
                rowf = fmaxf(rf.x, rf.y);
            }
            // ---- Cols: reduce-scatter over gr bits (xor 4, 8) + butterfly (16) ----
            float colf;
            {
                uint32_t v4[2];
                #pragma unroll
                for (int j = 0; j < 2; ++j) {
                    uint32_t s = p0b ? cm[j] : cm[j + 2];
                    uint32_t k = p0b ? cm[j + 2] : cm[j];
                    v4[j] = hmax2u(k, __shfl_xor_sync(0xffffffffu, s, 4));
                }
                uint32_t s = p1b ? v4[0] : v4[1];
                uint32_t k = p1b ? v4[1] : v4[0];
                uint32_t v2 = hmax2u(k, __shfl_xor_sync(0xffffffffu, s, 8));
                uint32_t cp = hmax2u(v2, __shfl_xor_sync(0xffffffffu, v2, 16));
                float2 cf = h2f2(cp);
                colf = 0.5f * (cf.x + cf.y);
            }

            part[kj] = rowf + colf;
        }

        // ---- Batched warp-sum of 8 partials (value-splitting reduction) ----
        float t4[4];
        {
            bool hi = (lane & 1);
            #pragma unroll
            for (int j = 0; j < 4; ++j) {
                float send = hi ? part[j] : part[j + 4];
                float keep = hi ? part[j + 4] : part[j];
                t4[j] = keep + __shfl_xor_sync(0xffffffffu, send, 1);
            }
        }
        float t2[2];
        {
            bool hi = (lane & 2);
            #pragma unroll
            for (int j = 0; j < 2; ++j) {
                float send = hi ? t4[j] : t4[j + 2];
                float keep = hi ? t4[j + 2] : t4[j];
                t2[j] = keep + __shfl_xor_sync(0xffffffffu, send, 2);
            }
        }
        float v;
        {
            bool hi = (lane & 4);
            float send = hi ? t2[0] : t2[1];
            float keep = hi ? t2[1] : t2[0];
            v = keep + __shfl_xor_sync(0xffffffffu, send, 4);
        }
        v += __shfl_xor_sync(0xffffffffu, v, 8);
        v += __shfl_xor_sync(0xffffffffu, v, 16);

        if (lane < 8) {
            int j = ((lane & 1) << 2) | (lane & 2) | ((lane >> 2) & 1);
            float res = 1.0f / (1.0f + __expf(v * -0.015625f));
            int k = k0 + g * 8 + j;
            out0[k] = res;
            out1[k] = res;
        }
    }
}

extern "C" void kernel_launch(void* const* d_in, const int* in_sizes, int n_in,
                              void* d_out, int out_size)
{
    const float* tgt = (const float*)d_in[0];   // [128, 768]
    const float* mem = (const float*)d_in[1];   // [2048, 768]
    float* out = (float*)d_out;                 // [2, 128, 2048]
    (void)in_sizes; (void)n_in; (void)out_size;

    cudaFuncSetAttribute(matcher_hmma,
                         cudaFuncAttributeMaxDynamicSharedMemorySize, SMEM_BYTES);
    matcher_hmma<<<1024, NTHR, SMEM_BYTES>>>(tgt, mem, out);
}